// round 14
// baseline (speedup 1.0000x reference)
#include <cuda_runtime.h>
#include <cuda_fp16.h>

#define Bb 8
#define Tt 2048
#define Cc 1024
#define Hh 64
#define BT (Bb*Tt)

// fp16 scratch stored as 32-bit words (2 halves per word)
// g_q16/g_k16: [token][32 dim-words], words PERMUTED within 8-word groups
//   (natural word w -> pos (w&~7)+2*(w&3)+((w>>2)&1), so (t, t+4) pairs adjacent)
// g_q16 additionally has softmax scale * log2(e) folded in.
__device__ unsigned g_q16[BT*32];
__device__ unsigned g_k16[BT*32];
// g_vT16: [dim 64][BT/2 token-words], tokens permuted within 16-token groups
__device__ unsigned g_vT16[64*(BT/2)];
// fused W (Wk|Wq|Wv) fp16: [n 192][512 k-words], words permuted per 8-group
__device__ unsigned g_wh16[192*512];
// split-KV partials + completion tickets (zero-init; reset by merging block)
__device__ float g_pO[2*BT*Hh];
__device__ float g_pm[2*BT];
__device__ float g_pl[2*BT];
__device__ int   g_tix[Bb*32];

#define WPERM(w) (((w) & ~7) + 2*((w) & 3) + (((w) >> 2) & 1))

__device__ __forceinline__ float fast_exp2(float x){
    float y;
    asm("ex2.approx.ftz.f32 %0, %1;" : "=f"(y) : "f"(x));
    return y;
}
__device__ __forceinline__ unsigned packh2(float lo, float hi){
    __half2 h = __floats2half2_rn(lo, hi);
    return *(unsigned*)&h;
}
__device__ __forceinline__ void mma_f16(float c[4], const unsigned a[4], const unsigned b[2]){
    asm volatile("mma.sync.aligned.m16n8k16.row.col.f32.f16.f16.f32 "
        "{%0,%1,%2,%3}, {%4,%5,%6,%7}, {%8,%9}, {%0,%1,%2,%3};"
        : "+f"(c[0]), "+f"(c[1]), "+f"(c[2]), "+f"(c[3])
        : "r"(a[0]), "r"(a[1]), "r"(a[2]), "r"(a[3]), "r"(b[0]), "r"(b[1]));
}
__device__ __forceinline__ void cp16(unsigned dst, const void* src){
    asm volatile("cp.async.cg.shared.global [%0], [%1], 16;" :: "r"(dst), "l"(src));
}
__device__ __forceinline__ void cp_commit(){ asm volatile("cp.async.commit_group;"); }
__device__ __forceinline__ void cp_wait0(){ asm volatile("cp.async.wait_group 0;"); }
__device__ __forceinline__ void cp_wait1(){ asm volatile("cp.async.wait_group 1;"); }
__device__ __forceinline__ void bar_sync(int id){
    asm volatile("bar.sync %0, 128;" :: "r"(id));
}
// acq_rel gpu-scope ticket: releases prior stores, acquires subsequent loads
__device__ __forceinline__ int ticket_acq_rel(int* p){
    int old;
    asm volatile("atom.acq_rel.gpu.add.s32 %0, [%1], 1;"
                 : "=r"(old) : "l"(p) : "memory");
    return old;
}

// ---------------------------------------------------------------------------
// One-shot W fuse + fp16 + transpose-to-[n][k] + word permutation.
// ---------------------------------------------------------------------------
__global__ __launch_bounds__(256) void cvt_w_kernel(
    const float* __restrict__ Wk,
    const float* __restrict__ Wq,
    const float* __restrict__ Wv)
{
    const int idx = blockIdx.x * 256 + threadIdx.x;   // 512*192 total
    const int n = idx % 192;
    const int w = idx / 192;                          // k-word 0..511
    const float* base = (n < 64) ? Wk : (n < 128) ? Wq : Wv;
    const int nn = (n < 64) ? n : (n < 128) ? n - 64 : n - 128;
    float lo = base[(size_t)(2*w)   * Hh + nn];
    float hi = base[(size_t)(2*w+1) * Hh + nn];
    g_wh16[(size_t)n * 512 + WPERM(w)] = packh2(lo, hi);
}

// ---------------------------------------------------------------------------
// Fused projection: [BT x 1024] @ W[1024 x 192], fp16 m16n8k16.
// 64x192 tile/block, 256 threads = 8 warps (2m x 4n), warp tile 32x48.
// V epilogue: smem transpose staging -> coalesced STG.128.
// ---------------------------------------------------------------------------
#define PXW 72                 // xsT stride words (==8 mod 32)
#define PXS (16*PXW)           // 1152 words per stage (16 k-words)
#define PWW 24                 // ws row stride words
#define PWS (192*PWW)          // 4608 words per stage
#define PROJ_SMEM ((2*PXS + 2*PWS)*4)   // 46080 B
#define VBW 72                 // vbuf half-stride per dim row

__global__ __launch_bounds__(256, 2) void proj_kernel(const float* __restrict__ x)
{
    const int row0 = blockIdx.x * 64;
    const int tid  = threadIdx.x;
    const int warp = tid >> 5;
    const int lane = tid & 31;
    const int mw = warp >> 2;      // 0..1
    const int wn = warp & 3;       // 0..3
    const int g = lane >> 2;
    const int t = lane & 3;

    extern __shared__ float sm[];
    unsigned* const xsm = (unsigned*)sm;                 // 2 stages xsT
    unsigned* const wsm = (unsigned*)sm + 2 * PXS;       // 2 stages ws
    const unsigned smb  = (unsigned)__cvta_generic_to_shared(sm);
    const unsigned wsmb = smb + 2u * PXS * 4u;

    float c[2][6][4];
#pragma unroll
    for (int mf = 0; mf < 2; mf++)
#pragma unroll
        for (int nf = 0; nf < 6; nf++)
#pragma unroll
            for (int i = 0; i < 4; i++) c[mf][nf][i] = 0.f;

    // x: 64 rows x 32 k fp32 = 512 float4, 2 per thread
    const int xr  = tid & 63;
    const int xcg = tid >> 6;      // 0..3
    const int qr  = (xr & ~15) + 2 * (xr & 7) + ((xr >> 3) & 1);   // slot(row)

    float4 xv[2];
    auto ldg_x = [&](int kc){
#pragma unroll
        for (int u = 0; u < 2; u++) {
            int c4 = (xcg * 2 + u) * 4;
            xv[u] = *(const float4*)&x[(size_t)(row0 + xr) * Cc + kc + c4];
        }
    };
    auto sts_x = [&](int s){
        unsigned* xs = xsm + s * PXS;
#pragma unroll
        for (int u = 0; u < 2; u++) {
            int w0 = (xcg * 2 + u) * 2;
            xs[(w0 + 0) * PXW + qr] = packh2(xv[u].x, xv[u].y);
            xs[(w0 + 1) * PXW + qr] = packh2(xv[u].z, xv[u].w);
        }
    };
    auto cp_w = [&](int kcw, int s){             // kcw = word base = it*16
        const unsigned wb = wsmb + (unsigned)(s * PWS) * 4u;
#pragma unroll
        for (int u = 0; u < 3; u++) {
            int f = tid + 256 * u;               // 768: 192 rows x 4 cp16
            int rr = f >> 2, wd4 = (f & 3) * 4;
            cp16(wb + (unsigned)(rr * PWW + wd4) * 4u,
                 &g_wh16[(size_t)rr * 512 + kcw + wd4]);
        }
        cp_commit();
    };

    ldg_x(0); cp_w(0, 0); sts_x(0);

    for (int it = 0; it < Cc / 32; it++) {
        cp_wait0();
        __syncthreads();
        const bool more = (it + 1 < Cc / 32);
        if (more) { ldg_x((it + 1) * 32); cp_w((it + 1) * 16, (it + 1) & 1); }

        const unsigned* xs = xsm + (it & 1) * PXS;
        const unsigned* ws = wsm + (it & 1) * PWS;
#pragma unroll
        for (int ks = 0; ks < 2; ks++) {
            const int k0 = ks * 8;
            unsigned b[6][2];
#pragma unroll
            for (int nf = 0; nf < 6; nf++) {
                uint2 bb = *(const uint2*)&ws[(wn * 48 + nf * 8 + g) * PWW + k0 + 2 * t];
                b[nf][0] = bb.x; b[nf][1] = bb.y;
            }
#pragma unroll
            for (int mf = 0; mf < 2; mf++) {
                const int sbase = mw * 32 + mf * 16 + 2 * g;
                uint2 a01 = *(const uint2*)&xs[(k0 + t) * PXW + sbase];
                uint2 a23 = *(const uint2*)&xs[(k0 + t + 4) * PXW + sbase];
                unsigned a[4] = { a01.x, a01.y, a23.x, a23.y };
#pragma unroll
                for (int nf = 0; nf < 6; nf++) mma_f16(c[mf][nf], a, b[nf]);
            }
        }
        if (more) sts_x((it + 1) & 1);
    }

    // ---- epilogue: K/Q direct permuted stores; V staged through smem ----
    const float QS = 0.125f * 1.44269504088896340736f;
    __syncthreads();                       // all smem compute reads done
    __half* const vbufh = (__half*)sm;     // [64 dims][VBW tokens]
#pragma unroll
    for (int mf = 0; mf < 2; mf++) {
        const int lr = mw * 32 + mf * 16 + g;     // local row in tile
        const int r0 = row0 + lr;
#pragma unroll
        for (int nf = 0; nf < 6; nf++) {
            const int col = wn * 48 + nf * 8 + 2 * t;
            float v0 = c[mf][nf][0], v1 = c[mf][nf][1];
            float v2 = c[mf][nf][2], v3 = c[mf][nf][3];
            if (col < 64) {
                const int wp = WPERM(col >> 1);
                g_k16[(size_t)r0 * 32 + wp]       = packh2(v0, v1);
                g_k16[(size_t)(r0 + 8) * 32 + wp] = packh2(v2, v3);
            } else if (col < 128) {
                const int wp = WPERM((col - 64) >> 1);
                g_q16[(size_t)r0 * 32 + wp]       = packh2(v0 * QS, v1 * QS);
                g_q16[(size_t)(r0 + 8) * 32 + wp] = packh2(v2 * QS, v3 * QS);
            } else {
                const int d0 = col - 128;
                vbufh[d0 * VBW + lr]           = __float2half_rn(v0);
                vbufh[(d0 + 1) * VBW + lr]     = __float2half_rn(v1);
                vbufh[d0 * VBW + lr + 8]       = __float2half_rn(v2);
                vbufh[(d0 + 1) * VBW + lr + 8] = __float2half_rn(v3);
            }
        }
    }
    __syncthreads();
    // cooperative permuted vT store: thread = (dim, 16-token group)
    {
        const int d   = tid >> 2;
        const int grp = tid & 3;
        const __half* src = vbufh + d * VBW + grp * 16;
        unsigned wbuf[8];
#pragma unroll
        for (int p = 0; p < 8; p++) {
            const int w = (p >> 1) + 4 * (p & 1);   // natural word stored at position p
            wbuf[p] = *(const unsigned*)(src + 2 * w);
        }
        const size_t base = (size_t)d * (BT / 2) + row0 / 2 + grp * 8;
        *(uint4*)&g_vT16[base]     = make_uint4(wbuf[0], wbuf[1], wbuf[2], wbuf[3]);
        *(uint4*)&g_vT16[base + 4] = make_uint4(wbuf[4], wbuf[5], wbuf[6], wbuf[7]);
    }
}

// ---------------------------------------------------------------------------
// Flash attention, fp16 m16n8k16. Split-KV x2 at block level + dual group.
// grid (32, 2, 8), 256 threads. Second-arriving block per (b,qt) merges the
// two halves (acq_rel ticket, L2-only loads) and writes the final output.
// ---------------------------------------------------------------------------
#define AW 40                  // K/VsT row stride words (==8 mod 32)
#define ATILE (64*AW)          // 2560 words
#define ATTN_SMEM (4*ATILE*4)  // 40960 B  (2 groups x (K, VsT))

__global__ __launch_bounds__(256, 2) void attn_kernel(float* __restrict__ out)
{
    const int qt   = (int)gridDim.x - 1 - (int)blockIdx.x;   // heavy first
    const int half = blockIdx.y;
    const int b    = blockIdx.z;
    const int q0   = qt * 64;
    const int tid  = threadIdx.x;
    const int warp = tid >> 5;
    const int lane = tid & 31;
    const int group = warp >> 2;
    const int wl   = warp & 3;
    const int wr0  = wl * 16;
    const int g = lane >> 2;
    const int t = lane & 3;
    const int gtid = tid & 127;

    extern __shared__ float sm[];
    __shared__ int s_last;
    const unsigned smb = (unsigned)__cvta_generic_to_shared(sm);

    // q A-frags: 4 k16-chunks x 4 regs, LDG.64 (scale pre-folded)
    unsigned qa[4][4];
    {
        const size_t rA = (size_t)b * Tt + q0 + wr0 + g;
#pragma unroll
        for (int kc = 0; kc < 4; kc++) {
            uint2 lo = *(const uint2*)&g_q16[rA * 32 + kc * 8 + 2 * t];
            uint2 hi = *(const uint2*)&g_q16[(rA + 8) * 32 + kc * 8 + 2 * t];
            qa[kc][0] = lo.x; qa[kc][2] = lo.y;
            qa[kc][1] = hi.x; qa[kc][3] = hi.y;
        }
    }

    float oc[8][4];
#pragma unroll
    for (int nf = 0; nf < 8; nf++)
#pragma unroll
        for (int i = 0; i < 4; i++) oc[nf][i] = 0.f;
    float m0 = -1e30f, m1 = -1e30f, l0 = 0.f, l1 = 0.f;

    const unsigned kb = smb + (unsigned)(group * 2 * ATILE) * 4u;
    const unsigned vb = kb + ATILE * 4u;

    auto load_k = [&](int n0){
        const size_t base = ((size_t)b * Tt + n0) * 32;
#pragma unroll
        for (int u = 0; u < 4; u++) {
            int f = gtid + 128 * u;
            int row = f >> 3, wd4 = (f & 7) * 4;
            cp16(kb + (unsigned)(row * AW + wd4) * 4u, &g_k16[base + (size_t)row * 32 + wd4]);
        }
        cp_commit();
    };
    auto load_v = [&](int n0){
        const size_t base = (size_t)b * (Tt / 2) + n0 / 2;
#pragma unroll
        for (int u = 0; u < 4; u++) {
            int f = gtid + 128 * u;
            int row = f >> 3, wd4 = (f & 7) * 4;
            cp16(vb + (unsigned)(row * AW + wd4) * 4u,
                 &g_vT16[(size_t)row * (BT / 2) + base + wd4]);
        }
        cp_commit();
    };

    const int nt = qt + 1;
    const int s  = (half == 0) ? 0 : (nt + 1) / 2;
    const int e  = (half == 0) ? (nt + 1) / 2 : nt;
    const int ng = (e - s > group) ? ((e - s - group + 1) >> 1) : 0;

    if (ng > 0) { load_k((s + group) * 64); load_v((s + group) * 64); }

    const unsigned* Ks = (const unsigned*)sm + group * 2 * ATILE;
    const unsigned* Vs = Ks + ATILE;

    for (int j = 0; j < ng; j++) {
        const int tile = s + 2 * j + group;

        cp_wait1();
        bar_sync(1 + group);

        float sc[8][4];
#pragma unroll
        for (int nf = 0; nf < 8; nf++)
#pragma unroll
            for (int i = 0; i < 4; i++) sc[nf][i] = 0.f;
#pragma unroll
        for (int kc = 0; kc < 4; kc++) {
#pragma unroll
            for (int nf = 0; nf < 8; nf++) {
                uint2 kk = *(const uint2*)&Ks[(nf * 8 + g) * AW + kc * 8 + 2 * t];
                unsigned bk[2] = { kk.x, kk.y };
                mma_f16(sc[nf], qa[kc], bk);
            }
        }
        bar_sync(1 + group);
        if (j + 1 < ng) load_k((tile + 2) * 64);

        if (tile == qt) {
#pragma unroll
            for (int nf = 0; nf < 8; nf++) {
                const int kl = nf * 8 + 2 * t;
                if (kl     > wr0 + g)     sc[nf][0] = -1e30f;
                if (kl + 1 > wr0 + g)     sc[nf][1] = -1e30f;
                if (kl     > wr0 + g + 8) sc[nf][2] = -1e30f;
                if (kl + 1 > wr0 + g + 8) sc[nf][3] = -1e30f;
            }
        }

        float mx0 = -1e30f, mx1 = -1e30f;
#pragma unroll
        for (int nf = 0; nf < 8; nf++) {
            mx0 = fmaxf(mx0, fmaxf(sc[nf][0], sc[nf][1]));
            mx1 = fmaxf(mx1, fmaxf(sc[nf][2], sc[nf][3]));
        }
        mx0 = fmaxf(mx0, __shfl_xor_sync(0xffffffffu, mx0, 1));
        mx0 = fmaxf(mx0, __shfl_xor_sync(0xffffffffu, mx0, 2));
        mx1 = fmaxf(mx1, __shfl_xor_sync(0xffffffffu, mx1, 1));
        mx1 = fmaxf(mx1, __shfl_xor_sync(0xffffffffu, mx1, 2));

        const float m0n = fmaxf(m0, mx0);
        const float m1n = fmaxf(m1, mx1);
        const float corr0 = fast_exp2(m0 - m0n);
        const float corr1 = fast_exp2(m1 - m1n);
        l0 *= corr0; l1 *= corr1;
#pragma unroll
        for (int nf = 0; nf < 8; nf++) {
            oc[nf][0] *= corr0; oc[nf][1] *= corr0;
            oc[nf][2] *= corr1; oc[nf][3] *= corr1;
        }
        unsigned pa[4][4];
#pragma unroll
        for (int h = 0; h < 4; h++) {
#pragma unroll
            for (int q2 = 0; q2 < 2; q2++) {
                const int nf = 2 * h + q2;
                float p0 = fast_exp2(sc[nf][0] - m0n);
                float p1 = fast_exp2(sc[nf][1] - m0n);
                float p2 = fast_exp2(sc[nf][2] - m1n);
                float p3 = fast_exp2(sc[nf][3] - m1n);
                l0 += p0 + p1;
                l1 += p2 + p3;
                pa[h][0 + 2 * q2] = packh2(p0, p1);
                pa[h][1 + 2 * q2] = packh2(p2, p3);
            }
        }
        m0 = m0n; m1 = m1n;

        cp_wait1();
        bar_sync(1 + group);

#pragma unroll
        for (int h = 0; h < 4; h++) {
#pragma unroll
            for (int nf = 0; nf < 8; nf++) {
                uint2 vv = *(const uint2*)&Vs[(nf * 8 + g) * AW + h * 8 + 2 * t];
                unsigned bv[2] = { vv.x, vv.y };
                mma_f16(oc[nf], pa[h], bv);
            }
        }
        bar_sync(1 + group);
        if (j + 1 < ng) load_v((tile + 2) * 64);
    }

    // ---- merge group partials, write block partial (unnormalized) ----
    __syncthreads();
    if (group == 1) {
        float* st = sm + (wl * 32 + lane) * 37;
#pragma unroll
        for (int nf = 0; nf < 8; nf++)
#pragma unroll
            for (int i = 0; i < 4; i++) st[nf * 4 + i] = oc[nf][i];
        st[32] = m0; st[33] = m1; st[34] = l0; st[35] = l1;
    }
    __syncthreads();
    if (group == 0) {
        const float* st = sm + (wl * 32 + lane) * 37;
        const float mb0 = st[32], mb1 = st[33], lb0 = st[34], lb1 = st[35];
        const float M0 = fmaxf(m0, mb0), M1 = fmaxf(m1, mb1);
        const float ca0 = fast_exp2(m0 - M0), cb0 = fast_exp2(mb0 - M0);
        const float ca1 = fast_exp2(m1 - M1), cb1 = fast_exp2(mb1 - M1);
        l0 = l0 * ca0 + lb0 * cb0;
        l1 = l1 * ca1 + lb1 * cb1;
#pragma unroll
        for (int nf = 0; nf < 8; nf++) {
            oc[nf][0] = oc[nf][0] * ca0 + st[nf * 4 + 0] * cb0;
            oc[nf][1] = oc[nf][1] * ca0 + st[nf * 4 + 1] * cb0;
            oc[nf][2] = oc[nf][2] * ca1 + st[nf * 4 + 2] * cb1;
            oc[nf][3] = oc[nf][3] * ca1 + st[nf * 4 + 3] * cb1;
        }
        l0 += __shfl_xor_sync(0xffffffffu, l0, 1);
        l0 += __shfl_xor_sync(0xffffffffu, l0, 2);
        l1 += __shfl_xor_sync(0xffffffffu, l1, 1);
        l1 += __shfl_xor_sync(0xffffffffu, l1, 2);

        const size_t row = (size_t)b * Tt + q0 + wr0 + g;
        float* po = g_pO + ((size_t)half * BT + row) * Hh;
#pragma unroll
        for (int nf = 0; nf < 8; nf++) {
            const int col = nf * 8 + 2 * t;
            *(float2*)&po[col]          = make_float2(oc[nf][0], oc[nf][1]);
            *(float2*)&po[8 * Hh + col] = make_float2(oc[nf][2], oc[nf][3]);
        }
        if (t == 0) {
            g_pm[half * BT + row] = M0;
            g_pl[half * BT + row] = l0;
            g_pm[half * BT + row + 8] = M1;
            g_pl[half * BT + row + 8] = l1;
        }
    }

    // ---- second-arriving block per (b,qt): merge halves, write out ----
    __syncthreads();                       // all partial stores issued block-wide
    if (tid == 0) {
        // acq_rel: releases this block's partials, acquires the peer's
        int old = ticket_acq_rel(&g_tix[b * 32 + qt]);
        s_last = (old == 1);
    }
    __syncthreads();
    if (s_last) {
        for (int i = tid; i < 64 * 16; i += 256) {
            const int r  = i >> 4;
            const int d4 = i & 15;
            const size_t row = (size_t)b * Tt + q0 + r;
            const float ma = __ldcg(&g_pm[row]),      mb = __ldcg(&g_pm[BT + row]);
            const float la = __ldcg(&g_pl[row]),      lb = __ldcg(&g_pl[BT + row]);
            const float M  = fmaxf(ma, mb);
            float ca = fast_exp2(ma - M);
            float cb = fast_exp2(mb - M);
            const float inv = 1.0f / (la * ca + lb * cb);
            ca *= inv; cb *= inv;
            float4 va  = __ldcg((const float4*)&g_pO[row * Hh] + d4);
            float4 vb2 = __ldcg((const float4*)&g_pO[(BT + row) * Hh] + d4);
            ((float4*)&out[row * Hh])[d4] =
                make_float4(va.x * ca + vb2.x * cb, va.y * ca + vb2.y * cb,
                            va.z * ca + vb2.z * cb, va.w * ca + vb2.w * cb);
        }
        if (tid == 0) g_tix[b * 32 + qt] = 0;   // reset for next graph replay
    }
}

extern "C" void kernel_launch(void* const* d_in, const int* in_sizes, int n_in,
                              void* d_out, int out_size)
{
    const float* x  = (const float*)d_in[0];
    const float* Wk = (const float*)d_in[1];
    const float* Wq = (const float*)d_in[2];
    const float* Wv = (const float*)d_in[3];
    float* out = (float*)d_out;

    cudaFuncSetAttribute(proj_kernel, cudaFuncAttributeMaxDynamicSharedMemorySize, PROJ_SMEM);
    cudaFuncSetAttribute(attn_kernel, cudaFuncAttributeMaxDynamicSharedMemorySize, ATTN_SMEM);

    cvt_w_kernel<<<512 * 192 / 256, 256>>>(Wk, Wq, Wv);

    proj_kernel<<<BT / 64, 256, PROJ_SMEM>>>(x);

    dim3 ag(Tt / 64, 2, Bb);
    attn_kernel<<<ag, 256, ATTN_SMEM>>>(out);
}

// round 15
// speedup vs baseline: 1.0254x; 1.0254x over previous
#include <cuda_runtime.h>
#include <cuda_fp16.h>

#define Bb 8
#define Tt 2048
#define Cc 1024
#define Hh 64
#define BT (Bb*Tt)

// fp16 scratch stored as 32-bit words (2 halves per word)
// g_q16/g_k16: [token][32 dim-words], words PERMUTED within 8-word groups
//   (natural word w -> pos (w&~7)+2*(w&3)+((w>>2)&1), so (t, t+4) pairs adjacent)
// g_q16 additionally has softmax scale * log2(e) folded in.
__device__ unsigned g_q16[BT*32];
__device__ unsigned g_k16[BT*32];
// g_vT16: [dim 64][BT/2 token-words], tokens permuted within 16-token groups
__device__ unsigned g_vT16[64*(BT/2)];
// fused W (Wk|Wq|Wv) fp16: [n 192][512 k-words], words permuted per 8-group
__device__ unsigned g_wh16[192*512];
// split-KV partials
__device__ float g_pO[2*BT*Hh];
__device__ float g_pm[2*BT];
__device__ float g_pl[2*BT];

#define WPERM(w) (((w) & ~7) + 2*((w) & 3) + (((w) >> 2) & 1))

__device__ __forceinline__ float fast_exp2(float x){
    float y;
    asm("ex2.approx.ftz.f32 %0, %1;" : "=f"(y) : "f"(x));
    return y;
}
__device__ __forceinline__ unsigned packh2(float lo, float hi){
    __half2 h = __floats2half2_rn(lo, hi);
    return *(unsigned*)&h;
}
__device__ __forceinline__ void mma_f16(float c[4], const unsigned a[4], const unsigned b[2]){
    asm volatile("mma.sync.aligned.m16n8k16.row.col.f32.f16.f16.f32 "
        "{%0,%1,%2,%3}, {%4,%5,%6,%7}, {%8,%9}, {%0,%1,%2,%3};"
        : "+f"(c[0]), "+f"(c[1]), "+f"(c[2]), "+f"(c[3])
        : "r"(a[0]), "r"(a[1]), "r"(a[2]), "r"(a[3]), "r"(b[0]), "r"(b[1]));
}
__device__ __forceinline__ void cp16(unsigned dst, const void* src){
    asm volatile("cp.async.cg.shared.global [%0], [%1], 16;" :: "r"(dst), "l"(src));
}
// L1-allocating variant: co-resident blocks on the same SM hit L1 for shared W
__device__ __forceinline__ void cp16_ca(unsigned dst, const void* src){
    asm volatile("cp.async.ca.shared.global [%0], [%1], 16;" :: "r"(dst), "l"(src));
}
__device__ __forceinline__ void cp_commit(){ asm volatile("cp.async.commit_group;"); }
__device__ __forceinline__ void cp_wait0(){ asm volatile("cp.async.wait_group 0;"); }
__device__ __forceinline__ void cp_wait1(){ asm volatile("cp.async.wait_group 1;"); }
__device__ __forceinline__ void bar_sync(int id){
    asm volatile("bar.sync %0, 128;" :: "r"(id));
}

// ---------------------------------------------------------------------------
// One-shot W fuse + fp16 + transpose-to-[n][k] + word permutation.
// ---------------------------------------------------------------------------
__global__ __launch_bounds__(256) void cvt_w_kernel(
    const float* __restrict__ Wk,
    const float* __restrict__ Wq,
    const float* __restrict__ Wv)
{
    const int idx = blockIdx.x * 256 + threadIdx.x;   // 512*192 total
    const int n = idx % 192;
    const int w = idx / 192;                          // k-word 0..511
    const float* base = (n < 64) ? Wk : (n < 128) ? Wq : Wv;
    const int nn = (n < 64) ? n : (n < 128) ? n - 64 : n - 128;
    float lo = base[(size_t)(2*w)   * Hh + nn];
    float hi = base[(size_t)(2*w+1) * Hh + nn];
    g_wh16[(size_t)n * 512 + WPERM(w)] = packh2(lo, hi);
}

// ---------------------------------------------------------------------------
// Fused projection: [BT x 1024] @ W[1024 x 192], fp16 m16n8k16.
// 64x192 tile/block, 256 threads = 8 warps (2m x 4n), warp tile 32x48.
// W stages via cp.async.ca (L1 reuse across co-resident blocks).
// V epilogue: smem transpose staging -> coalesced STG.128.
// ---------------------------------------------------------------------------
#define PXW 72                 // xsT stride words (==8 mod 32)
#define PXS (16*PXW)           // 1152 words per stage (16 k-words)
#define PWW 24                 // ws row stride words
#define PWS (192*PWW)          // 4608 words per stage
#define PROJ_SMEM ((2*PXS + 2*PWS)*4)   // 46080 B
#define VBW 72                 // vbuf half-stride per dim row

__global__ __launch_bounds__(256, 2) void proj_kernel(const float* __restrict__ x)
{
    const int row0 = blockIdx.x * 64;
    const int tid  = threadIdx.x;
    const int warp = tid >> 5;
    const int lane = tid & 31;
    const int mw = warp >> 2;      // 0..1
    const int wn = warp & 3;       // 0..3
    const int g = lane >> 2;
    const int t = lane & 3;

    extern __shared__ float sm[];
    unsigned* const xsm = (unsigned*)sm;                 // 2 stages xsT
    unsigned* const wsm = (unsigned*)sm + 2 * PXS;       // 2 stages ws
    const unsigned smb  = (unsigned)__cvta_generic_to_shared(sm);
    const unsigned wsmb = smb + 2u * PXS * 4u;

    float c[2][6][4];
#pragma unroll
    for (int mf = 0; mf < 2; mf++)
#pragma unroll
        for (int nf = 0; nf < 6; nf++)
#pragma unroll
            for (int i = 0; i < 4; i++) c[mf][nf][i] = 0.f;

    // x: 64 rows x 32 k fp32 = 512 float4, 2 per thread
    const int xr  = tid & 63;
    const int xcg = tid >> 6;      // 0..3
    const int qr  = (xr & ~15) + 2 * (xr & 7) + ((xr >> 3) & 1);   // slot(row)

    float4 xv[2];
    auto ldg_x = [&](int kc){
#pragma unroll
        for (int u = 0; u < 2; u++) {
            int c4 = (xcg * 2 + u) * 4;
            xv[u] = *(const float4*)&x[(size_t)(row0 + xr) * Cc + kc + c4];
        }
    };
    auto sts_x = [&](int s){
        unsigned* xs = xsm + s * PXS;
#pragma unroll
        for (int u = 0; u < 2; u++) {
            int w0 = (xcg * 2 + u) * 2;
            xs[(w0 + 0) * PXW + qr] = packh2(xv[u].x, xv[u].y);
            xs[(w0 + 1) * PXW + qr] = packh2(xv[u].z, xv[u].w);
        }
    };
    auto cp_w = [&](int kcw, int s){             // kcw = word base = it*16
        const unsigned wb = wsmb + (unsigned)(s * PWS) * 4u;
#pragma unroll
        for (int u = 0; u < 3; u++) {
            int f = tid + 256 * u;               // 768: 192 rows x 4 cp16
            int rr = f >> 2, wd4 = (f & 3) * 4;
            cp16_ca(wb + (unsigned)(rr * PWW + wd4) * 4u,
                    &g_wh16[(size_t)rr * 512 + kcw + wd4]);
        }
        cp_commit();
    };

    ldg_x(0); cp_w(0, 0); sts_x(0);

    for (int it = 0; it < Cc / 32; it++) {
        cp_wait0();
        __syncthreads();
        const bool more = (it + 1 < Cc / 32);
        if (more) { ldg_x((it + 1) * 32); cp_w((it + 1) * 16, (it + 1) & 1); }

        const unsigned* xs = xsm + (it & 1) * PXS;
        const unsigned* ws = wsm + (it & 1) * PWS;
#pragma unroll
        for (int ks = 0; ks < 2; ks++) {
            const int k0 = ks * 8;
            unsigned b[6][2];
#pragma unroll
            for (int nf = 0; nf < 6; nf++) {
                uint2 bb = *(const uint2*)&ws[(wn * 48 + nf * 8 + g) * PWW + k0 + 2 * t];
                b[nf][0] = bb.x; b[nf][1] = bb.y;
            }
#pragma unroll
            for (int mf = 0; mf < 2; mf++) {
                const int sbase = mw * 32 + mf * 16 + 2 * g;
                uint2 a01 = *(const uint2*)&xs[(k0 + t) * PXW + sbase];
                uint2 a23 = *(const uint2*)&xs[(k0 + t + 4) * PXW + sbase];
                unsigned a[4] = { a01.x, a01.y, a23.x, a23.y };
#pragma unroll
                for (int nf = 0; nf < 6; nf++) mma_f16(c[mf][nf], a, b[nf]);
            }
        }
        if (more) sts_x((it + 1) & 1);
    }

    // ---- epilogue: K/Q direct permuted stores; V staged through smem ----
    const float QS = 0.125f * 1.44269504088896340736f;
    __syncthreads();                       // all smem compute reads done
    __half* const vbufh = (__half*)sm;     // [64 dims][VBW tokens]
#pragma unroll
    for (int mf = 0; mf < 2; mf++) {
        const int lr = mw * 32 + mf * 16 + g;     // local row in tile
        const int r0 = row0 + lr;
#pragma unroll
        for (int nf = 0; nf < 6; nf++) {
            const int col = wn * 48 + nf * 8 + 2 * t;
            float v0 = c[mf][nf][0], v1 = c[mf][nf][1];
            float v2 = c[mf][nf][2], v3 = c[mf][nf][3];
            if (col < 64) {
                const int wp = WPERM(col >> 1);
                g_k16[(size_t)r0 * 32 + wp]       = packh2(v0, v1);
                g_k16[(size_t)(r0 + 8) * 32 + wp] = packh2(v2, v3);
            } else if (col < 128) {
                const int wp = WPERM((col - 64) >> 1);
                g_q16[(size_t)r0 * 32 + wp]       = packh2(v0 * QS, v1 * QS);
                g_q16[(size_t)(r0 + 8) * 32 + wp] = packh2(v2 * QS, v3 * QS);
            } else {
                const int d0 = col - 128;
                vbufh[d0 * VBW + lr]           = __float2half_rn(v0);
                vbufh[(d0 + 1) * VBW + lr]     = __float2half_rn(v1);
                vbufh[d0 * VBW + lr + 8]       = __float2half_rn(v2);
                vbufh[(d0 + 1) * VBW + lr + 8] = __float2half_rn(v3);
            }
        }
    }
    __syncthreads();
    // cooperative permuted vT store: thread = (dim, 16-token group)
    {
        const int d   = tid >> 2;
        const int grp = tid & 3;
        const __half* src = vbufh + d * VBW + grp * 16;
        unsigned wbuf[8];
#pragma unroll
        for (int p = 0; p < 8; p++) {
            const int w = (p >> 1) + 4 * (p & 1);   // natural word stored at position p
            wbuf[p] = *(const unsigned*)(src + 2 * w);
        }
        const size_t base = (size_t)d * (BT / 2) + row0 / 2 + grp * 8;
        *(uint4*)&g_vT16[base]     = make_uint4(wbuf[0], wbuf[1], wbuf[2], wbuf[3]);
        *(uint4*)&g_vT16[base + 4] = make_uint4(wbuf[4], wbuf[5], wbuf[6], wbuf[7]);
    }
}

// ---------------------------------------------------------------------------
// Flash attention, fp16 m16n8k16. Split-KV x2 at block level + dual group.
// grid (32, 2, 8), 256 threads. (Byte-for-byte R13.)
// ---------------------------------------------------------------------------
#define AW 40                  // K/VsT row stride words (==8 mod 32)
#define ATILE (64*AW)          // 2560 words
#define ATTN_SMEM (4*ATILE*4)  // 40960 B  (2 groups x (K, VsT))

__global__ __launch_bounds__(256, 2) void attn_kernel()
{
    const int qt   = (int)gridDim.x - 1 - (int)blockIdx.x;   // heavy first
    const int half = blockIdx.y;
    const int b    = blockIdx.z;
    const int q0   = qt * 64;
    const int tid  = threadIdx.x;
    const int warp = tid >> 5;
    const int lane = tid & 31;
    const int group = warp >> 2;
    const int wl   = warp & 3;
    const int wr0  = wl * 16;
    const int g = lane >> 2;
    const int t = lane & 3;
    const int gtid = tid & 127;

    extern __shared__ float sm[];
    const unsigned smb = (unsigned)__cvta_generic_to_shared(sm);

    // q A-frags: 4 k16-chunks x 4 regs, LDG.64 (scale pre-folded)
    unsigned qa[4][4];
    {
        const size_t rA = (size_t)b * Tt + q0 + wr0 + g;
#pragma unroll
        for (int kc = 0; kc < 4; kc++) {
            uint2 lo = *(const uint2*)&g_q16[rA * 32 + kc * 8 + 2 * t];
            uint2 hi = *(const uint2*)&g_q16[(rA + 8) * 32 + kc * 8 + 2 * t];
            qa[kc][0] = lo.x; qa[kc][2] = lo.y;
            qa[kc][1] = hi.x; qa[kc][3] = hi.y;
        }
    }

    float oc[8][4];
#pragma unroll
    for (int nf = 0; nf < 8; nf++)
#pragma unroll
        for (int i = 0; i < 4; i++) oc[nf][i] = 0.f;
    float m0 = -1e30f, m1 = -1e30f, l0 = 0.f, l1 = 0.f;

    const unsigned kb = smb + (unsigned)(group * 2 * ATILE) * 4u;
    const unsigned vb = kb + ATILE * 4u;

    auto load_k = [&](int n0){
        const size_t base = ((size_t)b * Tt + n0) * 32;
#pragma unroll
        for (int u = 0; u < 4; u++) {
            int f = gtid + 128 * u;
            int row = f >> 3, wd4 = (f & 7) * 4;
            cp16(kb + (unsigned)(row * AW + wd4) * 4u, &g_k16[base + (size_t)row * 32 + wd4]);
        }
        cp_commit();
    };
    auto load_v = [&](int n0){
        const size_t base = (size_t)b * (Tt / 2) + n0 / 2;
#pragma unroll
        for (int u = 0; u < 4; u++) {
            int f = gtid + 128 * u;
            int row = f >> 3, wd4 = (f & 7) * 4;
            cp16(vb + (unsigned)(row * AW + wd4) * 4u,
                 &g_vT16[(size_t)row * (BT / 2) + base + wd4]);
        }
        cp_commit();
    };

    const int nt = qt + 1;
    const int s  = (half == 0) ? 0 : (nt + 1) / 2;
    const int e  = (half == 0) ? (nt + 1) / 2 : nt;
    const int ng = (e - s > group) ? ((e - s - group + 1) >> 1) : 0;

    if (ng > 0) { load_k((s + group) * 64); load_v((s + group) * 64); }

    const unsigned* Ks = (const unsigned*)sm + group * 2 * ATILE;
    const unsigned* Vs = Ks + ATILE;

    for (int j = 0; j < ng; j++) {
        const int tile = s + 2 * j + group;

        cp_wait1();
        bar_sync(1 + group);

        float sc[8][4];
#pragma unroll
        for (int nf = 0; nf < 8; nf++)
#pragma unroll
            for (int i = 0; i < 4; i++) sc[nf][i] = 0.f;
#pragma unroll
        for (int kc = 0; kc < 4; kc++) {
#pragma unroll
            for (int nf = 0; nf < 8; nf++) {
                uint2 kk = *(const uint2*)&Ks[(nf * 8 + g) * AW + kc * 8 + 2 * t];
                unsigned bk[2] = { kk.x, kk.y };
                mma_f16(sc[nf], qa[kc], bk);
            }
        }
        bar_sync(1 + group);
        if (j + 1 < ng) load_k((tile + 2) * 64);

        if (tile == qt) {
#pragma unroll
            for (int nf = 0; nf < 8; nf++) {
                const int kl = nf * 8 + 2 * t;
                if (kl     > wr0 + g)     sc[nf][0] = -1e30f;
                if (kl + 1 > wr0 + g)     sc[nf][1] = -1e30f;
                if (kl     > wr0 + g + 8) sc[nf][2] = -1e30f;
                if (kl + 1 > wr0 + g + 8) sc[nf][3] = -1e30f;
            }
        }

        float mx0 = -1e30f, mx1 = -1e30f;
#pragma unroll
        for (int nf = 0; nf < 8; nf++) {
            mx0 = fmaxf(mx0, fmaxf(sc[nf][0], sc[nf][1]));
            mx1 = fmaxf(mx1, fmaxf(sc[nf][2], sc[nf][3]));
        }
        mx0 = fmaxf(mx0, __shfl_xor_sync(0xffffffffu, mx0, 1));
        mx0 = fmaxf(mx0, __shfl_xor_sync(0xffffffffu, mx0, 2));
        mx1 = fmaxf(mx1, __shfl_xor_sync(0xffffffffu, mx1, 1));
        mx1 = fmaxf(mx1, __shfl_xor_sync(0xffffffffu, mx1, 2));

        const float m0n = fmaxf(m0, mx0);
        const float m1n = fmaxf(m1, mx1);
        const float corr0 = fast_exp2(m0 - m0n);
        const float corr1 = fast_exp2(m1 - m1n);
        l0 *= corr0; l1 *= corr1;
#pragma unroll
        for (int nf = 0; nf < 8; nf++) {
            oc[nf][0] *= corr0; oc[nf][1] *= corr0;
            oc[nf][2] *= corr1; oc[nf][3] *= corr1;
        }
        unsigned pa[4][4];
#pragma unroll
        for (int h = 0; h < 4; h++) {
#pragma unroll
            for (int q2 = 0; q2 < 2; q2++) {
                const int nf = 2 * h + q2;
                float p0 = fast_exp2(sc[nf][0] - m0n);
                float p1 = fast_exp2(sc[nf][1] - m0n);
                float p2 = fast_exp2(sc[nf][2] - m1n);
                float p3 = fast_exp2(sc[nf][3] - m1n);
                l0 += p0 + p1;
                l1 += p2 + p3;
                pa[h][0 + 2 * q2] = packh2(p0, p1);
                pa[h][1 + 2 * q2] = packh2(p2, p3);
            }
        }
        m0 = m0n; m1 = m1n;

        cp_wait1();
        bar_sync(1 + group);

#pragma unroll
        for (int h = 0; h < 4; h++) {
#pragma unroll
            for (int nf = 0; nf < 8; nf++) {
                uint2 vv = *(const uint2*)&Vs[(nf * 8 + g) * AW + h * 8 + 2 * t];
                unsigned bv[2] = { vv.x, vv.y };
                mma_f16(oc[nf], pa[h], bv);
            }
        }
        bar_sync(1 + group);
        if (j + 1 < ng) load_v((tile + 2) * 64);
    }

    // ---- merge group partials, write block partial (unnormalized) ----
    __syncthreads();
    if (group == 1) {
        float* st = sm + (wl * 32 + lane) * 37;
#pragma unroll
        for (int nf = 0; nf < 8; nf++)
#pragma unroll
            for (int i = 0; i < 4; i++) st[nf * 4 + i] = oc[nf][i];
        st[32] = m0; st[33] = m1; st[34] = l0; st[35] = l1;
    }
    __syncthreads();
    if (group == 0) {
        const float* st = sm + (wl * 32 + lane) * 37;
        const float mb0 = st[32], mb1 = st[33], lb0 = st[34], lb1 = st[35];
        const float M0 = fmaxf(m0, mb0), M1 = fmaxf(m1, mb1);
        const float ca0 = fast_exp2(m0 - M0), cb0 = fast_exp2(mb0 - M0);
        const float ca1 = fast_exp2(m1 - M1), cb1 = fast_exp2(mb1 - M1);
        l0 = l0 * ca0 + lb0 * cb0;
        l1 = l1 * ca1 + lb1 * cb1;
#pragma unroll
        for (int nf = 0; nf < 8; nf++) {
            oc[nf][0] = oc[nf][0] * ca0 + st[nf * 4 + 0] * cb0;
            oc[nf][1] = oc[nf][1] * ca0 + st[nf * 4 + 1] * cb0;
            oc[nf][2] = oc[nf][2] * ca1 + st[nf * 4 + 2] * cb1;
            oc[nf][3] = oc[nf][3] * ca1 + st[nf * 4 + 3] * cb1;
        }
        l0 += __shfl_xor_sync(0xffffffffu, l0, 1);
        l0 += __shfl_xor_sync(0xffffffffu, l0, 2);
        l1 += __shfl_xor_sync(0xffffffffu, l1, 1);
        l1 += __shfl_xor_sync(0xffffffffu, l1, 2);

        const size_t row = (size_t)b * Tt + q0 + wr0 + g;
        float* po = g_pO + ((size_t)half * BT + row) * Hh;
#pragma unroll
        for (int nf = 0; nf < 8; nf++) {
            const int col = nf * 8 + 2 * t;
            *(float2*)&po[col]          = make_float2(oc[nf][0], oc[nf][1]);
            *(float2*)&po[8 * Hh + col] = make_float2(oc[nf][2], oc[nf][3]);
        }
        if (t == 0) {
            g_pm[half * BT + row] = M0;
            g_pl[half * BT + row] = l0;
            g_pm[half * BT + row + 8] = M1;
            g_pl[half * BT + row + 8] = l1;
        }
    }
}

// ---------------------------------------------------------------------------
// Merge the two KV halves + normalize. Two float4 per thread, L2-direct loads.
// ---------------------------------------------------------------------------
__global__ __launch_bounds__(256) void merge_kernel(float* __restrict__ out)
{
    const int idx = blockIdx.x * 256 + threadIdx.x;   // BT*8 total
    const int row = idx >> 3;
    const int d8  = (idx & 7) * 2;                    // float4 pair d8, d8+1
    const float ma = __ldcg(&g_pm[row]),  mb = __ldcg(&g_pm[BT + row]);
    const float la = __ldcg(&g_pl[row]),  lb = __ldcg(&g_pl[BT + row]);
    const float M  = fmaxf(ma, mb);
    float ca = fast_exp2(ma - M);
    float cb = fast_exp2(mb - M);
    const float inv = 1.0f / (la * ca + lb * cb);
    ca *= inv; cb *= inv;
    const float4* oa = (const float4*)&g_pO[(size_t)row * Hh];
    const float4* ob = (const float4*)&g_pO[(size_t)(BT + row) * Hh];
    float4* po = (float4*)&out[(size_t)row * Hh];
#pragma unroll
    for (int u = 0; u < 2; u++) {
        float4 va = __ldcg(oa + d8 + u);
        float4 vb = __ldcg(ob + d8 + u);
        po[d8 + u] = make_float4(va.x * ca + vb.x * cb, va.y * ca + vb.y * cb,
                                 va.z * ca + vb.z * cb, va.w * ca + vb.w * cb);
    }
}

extern "C" void kernel_launch(void* const* d_in, const int* in_sizes, int n_in,
                              void* d_out, int out_size)
{
    const float* x  = (const float*)d_in[0];
    const float* Wk = (const float*)d_in[1];
    const float* Wq = (const float*)d_in[2];
    const float* Wv = (const float*)d_in[3];
    float* out = (float*)d_out;

    cudaFuncSetAttribute(proj_kernel, cudaFuncAttributeMaxDynamicSharedMemorySize, PROJ_SMEM);
    cudaFuncSetAttribute(attn_kernel, cudaFuncAttributeMaxDynamicSharedMemorySize, ATTN_SMEM);

    cvt_w_kernel<<<512 * 192 / 256, 256>>>(Wk, Wq, Wv);

    proj_kernel<<<BT / 64, 256, PROJ_SMEM>>>(x);

    dim3 ag(Tt / 64, 2, Bb);
    attn_kernel<<<ag, 256, ATTN_SMEM>>>();

    merge_kernel<<<BT * 8 / 256, 256>>>(out);
}

// round 16
// speedup vs baseline: 1.0773x; 1.0506x over previous
#include <cuda_runtime.h>
#include <cuda_fp16.h>

#define Bb 8
#define Tt 2048
#define Cc 1024
#define Hh 64
#define BT (Bb*Tt)

// fp16 scratch stored as 32-bit words (2 halves per word)
// g_q16/g_k16: [token][32 dim-words], words PERMUTED within 8-word groups
//   (natural word w -> pos (w&~7)+2*(w&3)+((w>>2)&1), so (t, t+4) pairs adjacent)
// g_q16 additionally has softmax scale * log2(e) folded in.
__device__ unsigned g_q16[BT*32];
__device__ unsigned g_k16[BT*32];
// g_vT16: [dim 64][BT/2 token-words], tokens permuted within 16-token groups
__device__ unsigned g_vT16[64*(BT/2)];
// fused W (Wk|Wq|Wv) fp16: [n 192][512 k-words], words permuted per 8-group
__device__ unsigned g_wh16[192*512];
// split-KV partials
__device__ float g_pO[2*BT*Hh];
__device__ float g_pm[2*BT];
__device__ float g_pl[2*BT];

#define WPERM(w) (((w) & ~7) + 2*((w) & 3) + (((w) >> 2) & 1))

__device__ __forceinline__ float fast_exp2(float x){
    float y;
    asm("ex2.approx.ftz.f32 %0, %1;" : "=f"(y) : "f"(x));
    return y;
}
__device__ __forceinline__ unsigned packh2(float lo, float hi){
    __half2 h = __floats2half2_rn(lo, hi);
    return *(unsigned*)&h;
}
__device__ __forceinline__ void mma_f16(float c[4], const unsigned a[4], const unsigned b[2]){
    asm volatile("mma.sync.aligned.m16n8k16.row.col.f32.f16.f16.f32 "
        "{%0,%1,%2,%3}, {%4,%5,%6,%7}, {%8,%9}, {%0,%1,%2,%3};"
        : "+f"(c[0]), "+f"(c[1]), "+f"(c[2]), "+f"(c[3])
        : "r"(a[0]), "r"(a[1]), "r"(a[2]), "r"(a[3]), "r"(b[0]), "r"(b[1]));
}
__device__ __forceinline__ void cp16(unsigned dst, const void* src){
    asm volatile("cp.async.cg.shared.global [%0], [%1], 16;" :: "r"(dst), "l"(src));
}
__device__ __forceinline__ void cp_commit(){ asm volatile("cp.async.commit_group;"); }
__device__ __forceinline__ void cp_wait0(){ asm volatile("cp.async.wait_group 0;"); }
__device__ __forceinline__ void cp_wait1(){ asm volatile("cp.async.wait_group 1;"); }
__device__ __forceinline__ void bar_sync(int id){
    asm volatile("bar.sync %0, 128;" :: "r"(id));
}

// ---------------------------------------------------------------------------
// One-shot W fuse + fp16 + transpose-to-[n][k] + word permutation.
// smem tile transpose: coalesced reads over n, sector-grouped writes over w.
// grid (6, 16): 32 n-rows x 32 k-words per block, 256 threads.
// ---------------------------------------------------------------------------
__global__ __launch_bounds__(256) void cvt_w_kernel(
    const float* __restrict__ Wk,
    const float* __restrict__ Wq,
    const float* __restrict__ Wv)
{
    __shared__ unsigned ts[32][33];        // [w-local][n-local], pad 33
    const int n0 = blockIdx.x * 32;
    const int w0 = blockIdx.y * 32;
    const int tid = threadIdx.x;

    // read phase: thread (nn = tid&31, wl = tid>>5); 4 w per thread
    {
        const int nn = tid & 31;
        const int wl = tid >> 5;
        const int n  = n0 + nn;
        const float* base = (n < 64) ? Wk : (n < 128) ? Wq : Wv;
        const int nc = (n < 64) ? n : (n < 128) ? n - 64 : n - 128;
#pragma unroll
        for (int i = 0; i < 4; i++) {
            int w = w0 + wl + 8 * i;
            float lo = base[(size_t)(2 * w)     * Hh + nc];
            float hi = base[(size_t)(2 * w + 1) * Hh + nc];
            ts[wl + 8 * i][nn] = packh2(lo, hi);
        }
    }
    __syncthreads();
    // write phase: thread (nl = tid>>3, q = tid&7); 4 permuted words per thread
    {
        const int nl = tid >> 3;
        const int q  = tid & 7;
        unsigned* dst = &g_wh16[(size_t)(n0 + nl) * 512 + w0];
        const int qp = 2 * (q & 3) + (q >> 2);          // WPERM within 8-group
#pragma unroll
        for (int i = 0; i < 4; i++)
            dst[8 * i + qp] = ts[q + 8 * i][nl];
    }
}

// ---------------------------------------------------------------------------
// Fused projection: [BT x 1024] @ W[1024 x 192], fp16 m16n8k16.
// 64x192 tile/block, 256 threads = 8 warps (2m x 4n), warp tile 32x48.
// V epilogue: smem transpose staging -> coalesced STG.128.
// ---------------------------------------------------------------------------
#define PXW 72                 // xsT stride words (==8 mod 32)
#define PXS (16*PXW)           // 1152 words per stage (16 k-words)
#define PWW 24                 // ws row stride words
#define PWS (192*PWW)          // 4608 words per stage
#define PROJ_SMEM ((2*PXS + 2*PWS)*4)   // 46080 B
#define VBW 72                 // vbuf half-stride per dim row

__global__ __launch_bounds__(256, 2) void proj_kernel(const float* __restrict__ x)
{
    const int row0 = blockIdx.x * 64;
    const int tid  = threadIdx.x;
    const int warp = tid >> 5;
    const int lane = tid & 31;
    const int mw = warp >> 2;      // 0..1
    const int wn = warp & 3;       // 0..3
    const int g = lane >> 2;
    const int t = lane & 3;

    extern __shared__ float sm[];
    unsigned* const xsm = (unsigned*)sm;                 // 2 stages xsT
    unsigned* const wsm = (unsigned*)sm + 2 * PXS;       // 2 stages ws
    const unsigned smb  = (unsigned)__cvta_generic_to_shared(sm);
    const unsigned wsmb = smb + 2u * PXS * 4u;

    float c[2][6][4];
#pragma unroll
    for (int mf = 0; mf < 2; mf++)
#pragma unroll
        for (int nf = 0; nf < 6; nf++)
#pragma unroll
            for (int i = 0; i < 4; i++) c[mf][nf][i] = 0.f;

    // x: 64 rows x 32 k fp32 = 512 float4, 2 per thread
    const int xr  = tid & 63;
    const int xcg = tid >> 6;      // 0..3
    const int qr  = (xr & ~15) + 2 * (xr & 7) + ((xr >> 3) & 1);   // slot(row)

    float4 xv[2];
    auto ldg_x = [&](int kc){
#pragma unroll
        for (int u = 0; u < 2; u++) {
            int c4 = (xcg * 2 + u) * 4;
            xv[u] = *(const float4*)&x[(size_t)(row0 + xr) * Cc + kc + c4];
        }
    };
    auto sts_x = [&](int s){
        unsigned* xs = xsm + s * PXS;
#pragma unroll
        for (int u = 0; u < 2; u++) {
            int w0 = (xcg * 2 + u) * 2;
            xs[(w0 + 0) * PXW + qr] = packh2(xv[u].x, xv[u].y);
            xs[(w0 + 1) * PXW + qr] = packh2(xv[u].z, xv[u].w);
        }
    };
    auto cp_w = [&](int kcw, int s){             // kcw = word base = it*16
        const unsigned wb = wsmb + (unsigned)(s * PWS) * 4u;
#pragma unroll
        for (int u = 0; u < 3; u++) {
            int f = tid + 256 * u;               // 768: 192 rows x 4 cp16
            int rr = f >> 2, wd4 = (f & 3) * 4;
            cp16(wb + (unsigned)(rr * PWW + wd4) * 4u,
                 &g_wh16[(size_t)rr * 512 + kcw + wd4]);
        }
        cp_commit();
    };

    ldg_x(0); cp_w(0, 0); sts_x(0);

    for (int it = 0; it < Cc / 32; it++) {
        cp_wait0();
        __syncthreads();
        const bool more = (it + 1 < Cc / 32);
        if (more) { ldg_x((it + 1) * 32); cp_w((it + 1) * 16, (it + 1) & 1); }

        const unsigned* xs = xsm + (it & 1) * PXS;
        const unsigned* ws = wsm + (it & 1) * PWS;
#pragma unroll
        for (int ks = 0; ks < 2; ks++) {
            const int k0 = ks * 8;
            unsigned b[6][2];
#pragma unroll
            for (int nf = 0; nf < 6; nf++) {
                uint2 bb = *(const uint2*)&ws[(wn * 48 + nf * 8 + g) * PWW + k0 + 2 * t];
                b[nf][0] = bb.x; b[nf][1] = bb.y;
            }
#pragma unroll
            for (int mf = 0; mf < 2; mf++) {
                const int sbase = mw * 32 + mf * 16 + 2 * g;
                uint2 a01 = *(const uint2*)&xs[(k0 + t) * PXW + sbase];
                uint2 a23 = *(const uint2*)&xs[(k0 + t + 4) * PXW + sbase];
                unsigned a[4] = { a01.x, a01.y, a23.x, a23.y };
#pragma unroll
                for (int nf = 0; nf < 6; nf++) mma_f16(c[mf][nf], a, b[nf]);
            }
        }
        if (more) sts_x((it + 1) & 1);
    }

    // ---- epilogue: K/Q direct permuted stores; V staged through smem ----
    const float QS = 0.125f * 1.44269504088896340736f;
    __syncthreads();                       // all smem compute reads done
    __half* const vbufh = (__half*)sm;     // [64 dims][VBW tokens]
#pragma unroll
    for (int mf = 0; mf < 2; mf++) {
        const int lr = mw * 32 + mf * 16 + g;     // local row in tile
        const int r0 = row0 + lr;
#pragma unroll
        for (int nf = 0; nf < 6; nf++) {
            const int col = wn * 48 + nf * 8 + 2 * t;
            float v0 = c[mf][nf][0], v1 = c[mf][nf][1];
            float v2 = c[mf][nf][2], v3 = c[mf][nf][3];
            if (col < 64) {
                const int wp = WPERM(col >> 1);
                g_k16[(size_t)r0 * 32 + wp]       = packh2(v0, v1);
                g_k16[(size_t)(r0 + 8) * 32 + wp] = packh2(v2, v3);
            } else if (col < 128) {
                const int wp = WPERM((col - 64) >> 1);
                g_q16[(size_t)r0 * 32 + wp]       = packh2(v0 * QS, v1 * QS);
                g_q16[(size_t)(r0 + 8) * 32 + wp] = packh2(v2 * QS, v3 * QS);
            } else {
                const int d0 = col - 128;
                vbufh[d0 * VBW + lr]           = __float2half_rn(v0);
                vbufh[(d0 + 1) * VBW + lr]     = __float2half_rn(v1);
                vbufh[d0 * VBW + lr + 8]       = __float2half_rn(v2);
                vbufh[(d0 + 1) * VBW + lr + 8] = __float2half_rn(v3);
            }
        }
    }
    __syncthreads();
    // cooperative permuted vT store: thread = (dim, 16-token group)
    {
        const int d   = tid >> 2;
        const int grp = tid & 3;
        const __half* src = vbufh + d * VBW + grp * 16;
        unsigned wbuf[8];
#pragma unroll
        for (int p = 0; p < 8; p++) {
            const int w = (p >> 1) + 4 * (p & 1);   // natural word stored at position p
            wbuf[p] = *(const unsigned*)(src + 2 * w);
        }
        const size_t base = (size_t)d * (BT / 2) + row0 / 2 + grp * 8;
        *(uint4*)&g_vT16[base]     = make_uint4(wbuf[0], wbuf[1], wbuf[2], wbuf[3]);
        *(uint4*)&g_vT16[base + 4] = make_uint4(wbuf[4], wbuf[5], wbuf[6], wbuf[7]);
    }
}

// ---------------------------------------------------------------------------
// Flash attention, fp16 m16n8k16. Split-KV x2 at block level + dual group.
// grid (32, 2, 8), 256 threads. (Byte-for-byte R13.)
// ---------------------------------------------------------------------------
#define AW 40                  // K/VsT row stride words (==8 mod 32)
#define ATILE (64*AW)          // 2560 words
#define ATTN_SMEM (4*ATILE*4)  // 40960 B  (2 groups x (K, VsT))

__global__ __launch_bounds__(256, 2) void attn_kernel()
{
    const int qt   = (int)gridDim.x - 1 - (int)blockIdx.x;   // heavy first
    const int half = blockIdx.y;
    const int b    = blockIdx.z;
    const int q0   = qt * 64;
    const int tid  = threadIdx.x;
    const int warp = tid >> 5;
    const int lane = tid & 31;
    const int group = warp >> 2;
    const int wl   = warp & 3;
    const int wr0  = wl * 16;
    const int g = lane >> 2;
    const int t = lane & 3;
    const int gtid = tid & 127;

    extern __shared__ float sm[];
    const unsigned smb = (unsigned)__cvta_generic_to_shared(sm);

    // q A-frags: 4 k16-chunks x 4 regs, LDG.64 (scale pre-folded)
    unsigned qa[4][4];
    {
        const size_t rA = (size_t)b * Tt + q0 + wr0 + g;
#pragma unroll
        for (int kc = 0; kc < 4; kc++) {
            uint2 lo = *(const uint2*)&g_q16[rA * 32 + kc * 8 + 2 * t];
            uint2 hi = *(const uint2*)&g_q16[(rA + 8) * 32 + kc * 8 + 2 * t];
            qa[kc][0] = lo.x; qa[kc][2] = lo.y;
            qa[kc][1] = hi.x; qa[kc][3] = hi.y;
        }
    }

    float oc[8][4];
#pragma unroll
    for (int nf = 0; nf < 8; nf++)
#pragma unroll
        for (int i = 0; i < 4; i++) oc[nf][i] = 0.f;
    float m0 = -1e30f, m1 = -1e30f, l0 = 0.f, l1 = 0.f;

    const unsigned kb = smb + (unsigned)(group * 2 * ATILE) * 4u;
    const unsigned vb = kb + ATILE * 4u;

    auto load_k = [&](int n0){
        const size_t base = ((size_t)b * Tt + n0) * 32;
#pragma unroll
        for (int u = 0; u < 4; u++) {
            int f = gtid + 128 * u;
            int row = f >> 3, wd4 = (f & 7) * 4;
            cp16(kb + (unsigned)(row * AW + wd4) * 4u, &g_k16[base + (size_t)row * 32 + wd4]);
        }
        cp_commit();
    };
    auto load_v = [&](int n0){
        const size_t base = (size_t)b * (Tt / 2) + n0 / 2;
#pragma unroll
        for (int u = 0; u < 4; u++) {
            int f = gtid + 128 * u;
            int row = f >> 3, wd4 = (f & 7) * 4;
            cp16(vb + (unsigned)(row * AW + wd4) * 4u,
                 &g_vT16[(size_t)row * (BT / 2) + base + wd4]);
        }
        cp_commit();
    };

    const int nt = qt + 1;
    const int s  = (half == 0) ? 0 : (nt + 1) / 2;
    const int e  = (half == 0) ? (nt + 1) / 2 : nt;
    const int ng = (e - s > group) ? ((e - s - group + 1) >> 1) : 0;

    if (ng > 0) { load_k((s + group) * 64); load_v((s + group) * 64); }

    const unsigned* Ks = (const unsigned*)sm + group * 2 * ATILE;
    const unsigned* Vs = Ks + ATILE;

    for (int j = 0; j < ng; j++) {
        const int tile = s + 2 * j + group;

        cp_wait1();
        bar_sync(1 + group);

        float sc[8][4];
#pragma unroll
        for (int nf = 0; nf < 8; nf++)
#pragma unroll
            for (int i = 0; i < 4; i++) sc[nf][i] = 0.f;
#pragma unroll
        for (int kc = 0; kc < 4; kc++) {
#pragma unroll
            for (int nf = 0; nf < 8; nf++) {
                uint2 kk = *(const uint2*)&Ks[(nf * 8 + g) * AW + kc * 8 + 2 * t];
                unsigned bk[2] = { kk.x, kk.y };
                mma_f16(sc[nf], qa[kc], bk);
            }
        }
        bar_sync(1 + group);
        if (j + 1 < ng) load_k((tile + 2) * 64);

        if (tile == qt) {
#pragma unroll
            for (int nf = 0; nf < 8; nf++) {
                const int kl = nf * 8 + 2 * t;
                if (kl     > wr0 + g)     sc[nf][0] = -1e30f;
                if (kl + 1 > wr0 + g)     sc[nf][1] = -1e30f;
                if (kl     > wr0 + g + 8) sc[nf][2] = -1e30f;
                if (kl + 1 > wr0 + g + 8) sc[nf][3] = -1e30f;
            }
        }

        float mx0 = -1e30f, mx1 = -1e30f;
#pragma unroll
        for (int nf = 0; nf < 8; nf++) {
            mx0 = fmaxf(mx0, fmaxf(sc[nf][0], sc[nf][1]));
            mx1 = fmaxf(mx1, fmaxf(sc[nf][2], sc[nf][3]));
        }
        mx0 = fmaxf(mx0, __shfl_xor_sync(0xffffffffu, mx0, 1));
        mx0 = fmaxf(mx0, __shfl_xor_sync(0xffffffffu, mx0, 2));
        mx1 = fmaxf(mx1, __shfl_xor_sync(0xffffffffu, mx1, 1));
        mx1 = fmaxf(mx1, __shfl_xor_sync(0xffffffffu, mx1, 2));

        const float m0n = fmaxf(m0, mx0);
        const float m1n = fmaxf(m1, mx1);
        const float corr0 = fast_exp2(m0 - m0n);
        const float corr1 = fast_exp2(m1 - m1n);
        l0 *= corr0; l1 *= corr1;
#pragma unroll
        for (int nf = 0; nf < 8; nf++) {
            oc[nf][0] *= corr0; oc[nf][1] *= corr0;
            oc[nf][2] *= corr1; oc[nf][3] *= corr1;
        }
        unsigned pa[4][4];
#pragma unroll
        for (int h = 0; h < 4; h++) {
#pragma unroll
            for (int q2 = 0; q2 < 2; q2++) {
                const int nf = 2 * h + q2;
                float p0 = fast_exp2(sc[nf][0] - m0n);
                float p1 = fast_exp2(sc[nf][1] - m0n);
                float p2 = fast_exp2(sc[nf][2] - m1n);
                float p3 = fast_exp2(sc[nf][3] - m1n);
                l0 += p0 + p1;
                l1 += p2 + p3;
                pa[h][0 + 2 * q2] = packh2(p0, p1);
                pa[h][1 + 2 * q2] = packh2(p2, p3);
            }
        }
        m0 = m0n; m1 = m1n;

        cp_wait1();
        bar_sync(1 + group);

#pragma unroll
        for (int h = 0; h < 4; h++) {
#pragma unroll
            for (int nf = 0; nf < 8; nf++) {
                uint2 vv = *(const uint2*)&Vs[(nf * 8 + g) * AW + h * 8 + 2 * t];
                unsigned bv[2] = { vv.x, vv.y };
                mma_f16(oc[nf], pa[h], bv);
            }
        }
        bar_sync(1 + group);
        if (j + 1 < ng) load_v((tile + 2) * 64);
    }

    // ---- merge group partials, write block partial (unnormalized) ----
    __syncthreads();
    if (group == 1) {
        float* st = sm + (wl * 32 + lane) * 37;
#pragma unroll
        for (int nf = 0; nf < 8; nf++)
#pragma unroll
            for (int i = 0; i < 4; i++) st[nf * 4 + i] = oc[nf][i];
        st[32] = m0; st[33] = m1; st[34] = l0; st[35] = l1;
    }
    __syncthreads();
    if (group == 0) {
        const float* st = sm + (wl * 32 + lane) * 37;
        const float mb0 = st[32], mb1 = st[33], lb0 = st[34], lb1 = st[35];
        const float M0 = fmaxf(m0, mb0), M1 = fmaxf(m1, mb1);
        const float ca0 = fast_exp2(m0 - M0), cb0 = fast_exp2(mb0 - M0);
        const float ca1 = fast_exp2(m1 - M1), cb1 = fast_exp2(mb1 - M1);
        l0 = l0 * ca0 + lb0 * cb0;
        l1 = l1 * ca1 + lb1 * cb1;
#pragma unroll
        for (int nf = 0; nf < 8; nf++) {
            oc[nf][0] = oc[nf][0] * ca0 + st[nf * 4 + 0] * cb0;
            oc[nf][1] = oc[nf][1] * ca0 + st[nf * 4 + 1] * cb0;
            oc[nf][2] = oc[nf][2] * ca1 + st[nf * 4 + 2] * cb1;
            oc[nf][3] = oc[nf][3] * ca1 + st[nf * 4 + 3] * cb1;
        }
        l0 += __shfl_xor_sync(0xffffffffu, l0, 1);
        l0 += __shfl_xor_sync(0xffffffffu, l0, 2);
        l1 += __shfl_xor_sync(0xffffffffu, l1, 1);
        l1 += __shfl_xor_sync(0xffffffffu, l1, 2);

        const size_t row = (size_t)b * Tt + q0 + wr0 + g;
        float* po = g_pO + ((size_t)half * BT + row) * Hh;
#pragma unroll
        for (int nf = 0; nf < 8; nf++) {
            const int col = nf * 8 + 2 * t;
            *(float2*)&po[col]          = make_float2(oc[nf][0], oc[nf][1]);
            *(float2*)&po[8 * Hh + col] = make_float2(oc[nf][2], oc[nf][3]);
        }
        if (t == 0) {
            g_pm[half * BT + row] = M0;
            g_pl[half * BT + row] = l0;
            g_pm[half * BT + row + 8] = M1;
            g_pl[half * BT + row + 8] = l1;
        }
    }
}

// ---------------------------------------------------------------------------
// Merge the two KV halves + normalize. One float4 of one row per thread.
// ---------------------------------------------------------------------------
__global__ __launch_bounds__(256) void merge_kernel(float* __restrict__ out)
{
    const int idx = blockIdx.x * 256 + threadIdx.x;   // BT*16 total
    const int row = idx >> 4;
    const int d4  = idx & 15;
    const float ma = g_pm[row],      mb = g_pm[BT + row];
    const float la = g_pl[row],      lb = g_pl[BT + row];
    const float M  = fmaxf(ma, mb);
    float ca = fast_exp2(ma - M);
    float cb = fast_exp2(mb - M);
    const float inv = 1.0f / (la * ca + lb * cb);
    ca *= inv; cb *= inv;
    float4 va = ((const float4*)&g_pO[(size_t)row * Hh])[d4];
    float4 vb = ((const float4*)&g_pO[(size_t)(BT + row) * Hh])[d4];
    ((float4*)&out[(size_t)row * Hh])[d4] =
        make_float4(va.x * ca + vb.x * cb, va.y * ca + vb.y * cb,
                    va.z * ca + vb.z * cb, va.w * ca + vb.w * cb);
}

extern "C" void kernel_launch(void* const* d_in, const int* in_sizes, int n_in,
                              void* d_out, int out_size)
{
    const float* x  = (const float*)d_in[0];
    const float* Wk = (const float*)d_in[1];
    const float* Wq = (const float*)d_in[2];
    const float* Wv = (const float*)d_in[3];
    float* out = (float*)d_out;

    cudaFuncSetAttribute(proj_kernel, cudaFuncAttributeMaxDynamicSharedMemorySize, PROJ_SMEM);
    cudaFuncSetAttribute(attn_kernel, cudaFuncAttributeMaxDynamicSharedMemorySize, ATTN_SMEM);

    dim3 cg(6, 16);
    cvt_w_kernel<<<cg, 256>>>(Wk, Wq, Wv);

    proj_kernel<<<BT / 64, 256, PROJ_SMEM>>>(x);

    dim3 ag(Tt / 64, 2, Bb);
    attn_kernel<<<ag, 256, ATTN_SMEM>>>();

    merge_kernel<<<BT * 16 / 256, 256>>>(out);
}